// round 1
// baseline (speedup 1.0000x reference)
#include <cuda_runtime.h>

#define S_LEN 2048
#define D_DIM 1024
#define H_NUM 16
#define HD    64
#define B_NUM 2
#define M_TOT (B_NUM * S_LEN)   // 4096

// Scratch (static device globals; no runtime allocation)
__device__ float g_Q[(size_t)M_TOT * D_DIM];
__device__ float g_K[(size_t)M_TOT * D_DIM];
__device__ float g_V[(size_t)M_TOT * D_DIM];
__device__ float g_A[(size_t)M_TOT * D_DIM];

// ---------------------------------------------------------------------------
// SGEMM: C[M,N] = A[M,K] @ B[K,N], all row-major fp32.
// 128x128 block tile, BK=8, 256 threads, 8x8 per thread (split 2x2 of 4x4
// micro-tiles at +0/+64 so smem reads are conflict-free lds.128).
// ---------------------------------------------------------------------------
__global__ __launch_bounds__(256) void sgemm128(const float* __restrict__ A,
                                                const float* __restrict__ B,
                                                float* __restrict__ C,
                                                int M, int N, int K)
{
    __shared__ __align__(16) float As[8][128];
    __shared__ __align__(16) float Bs[8][128];

    const int tid = threadIdx.x;
    const int ty = tid >> 4;        // 0..15
    const int tx = tid & 15;        // 0..15
    const int br = blockIdx.y;
    const int bc = blockIdx.x;

    // global-load assignments
    const int arow = tid >> 1;            // 0..127
    const int acol = (tid & 1) * 4;       // 0 or 4
    const int brow = tid >> 5;            // 0..7
    const int bcol = (tid & 31) * 4;      // 0..124

    const float* Aptr = A + (size_t)(br * 128 + arow) * K + acol;
    const float* Bptr = B + (size_t)brow * N + bc * 128 + bcol;

    float acc[8][8];
#pragma unroll
    for (int i = 0; i < 8; i++)
#pragma unroll
        for (int j = 0; j < 8; j++) acc[i][j] = 0.0f;

    for (int kt = 0; kt < K; kt += 8) {
        float4 av = *(const float4*)(Aptr + kt);
        float4 bv = *(const float4*)(Bptr + (size_t)kt * N);
        __syncthreads();
        As[acol + 0][arow] = av.x;
        As[acol + 1][arow] = av.y;
        As[acol + 2][arow] = av.z;
        As[acol + 3][arow] = av.w;
        *(float4*)&Bs[brow][bcol] = bv;
        __syncthreads();

#pragma unroll
        for (int k = 0; k < 8; k++) {
            float4 a0 = *(const float4*)&As[k][ty * 4];
            float4 a1 = *(const float4*)&As[k][64 + ty * 4];
            float4 b0 = *(const float4*)&Bs[k][tx * 4];
            float4 b1 = *(const float4*)&Bs[k][64 + tx * 4];
            float ra[8] = {a0.x, a0.y, a0.z, a0.w, a1.x, a1.y, a1.z, a1.w};
            float rb[8] = {b0.x, b0.y, b0.z, b0.w, b1.x, b1.y, b1.z, b1.w};
#pragma unroll
            for (int i = 0; i < 8; i++)
#pragma unroll
                for (int j = 0; j < 8; j++)
                    acc[i][j] += ra[i] * rb[j];
        }
    }

#pragma unroll
    for (int i = 0; i < 8; i++) {
        int row = br * 128 + (i / 4) * 64 + ty * 4 + (i % 4);
        float4 v0 = make_float4(acc[i][0], acc[i][1], acc[i][2], acc[i][3]);
        float4 v1 = make_float4(acc[i][4], acc[i][5], acc[i][6], acc[i][7]);
        *(float4*)(C + (size_t)row * N + bc * 128 + tx * 4)      = v0;
        *(float4*)(C + (size_t)row * N + bc * 128 + 64 + tx * 4) = v1;
    }
}

// ---------------------------------------------------------------------------
// Flash attention (fp32, causal). One block per (q-tile of 64, head, batch).
// Q/K/V live in (B,S,D) layout; head h occupies columns [h*64, h*64+64).
// 256 threads = 16x16; each thread owns a 4x4 patch of the 64x64 tile.
// K tile is stored transposed ([d][c]) so both GEMM phases read smem as
// conflict-free lds.128.
// ---------------------------------------------------------------------------
#define PAD 68   // row stride (floats) for 64-wide tiles; 68*4B = 16B-aligned

__global__ __launch_bounds__(256) void flash_fp32(const float* __restrict__ Q,
                                                  const float* __restrict__ K,
                                                  const float* __restrict__ V,
                                                  float* __restrict__ Ao)
{
    extern __shared__ __align__(16) float sm[];
    float* Qs   = sm;                  // [64][PAD]  Q tile, row-major
    float* KV   = Qs + 64 * PAD;       // [64][PAD]  K^T ([d][c]) then V ([k][d])
    float* Ps   = KV + 64 * PAD;       // [64][PAD]  P tile
    float* red  = Ps + 64 * PAD;       // [64][16]   row reductions
    float* mrow = red + 64 * 16;       // [64]
    float* lrow = mrow + 64;           // [64]
    float* crow = lrow + 64;           // [64]

    const int tid = threadIdx.x;
    const int ty = tid >> 4;
    const int tx = tid & 15;
    const int q0 = blockIdx.x * 64;
    const int h  = blockIdx.y;
    const int b  = blockIdx.z;
    const size_t baseoff = (size_t)b * S_LEN * D_DIM + (size_t)h * HD;

    // Load Q tile: thread -> row tid/4, 16 consecutive floats
    {
        int r  = tid >> 2;
        int d0 = (tid & 3) * 16;
        const float* src = Q + baseoff + (size_t)(q0 + r) * D_DIM + d0;
#pragma unroll
        for (int i = 0; i < 4; i++)
            *(float4*)&Qs[r * PAD + d0 + i * 4] = *(const float4*)(src + i * 4);
    }
    if (tid < 64) { mrow[tid] = -1e30f; lrow[tid] = 0.0f; }

    float Oa[4][4];
#pragma unroll
    for (int i = 0; i < 4; i++)
#pragma unroll
        for (int j = 0; j < 4; j++) Oa[i][j] = 0.0f;

    const int nt = q0 / 64 + 1;   // causal: only tiles with k0 <= q0

    for (int t = 0; t < nt; t++) {
        const int k0 = t * 64;

        __syncthreads();  // (a) prev-iteration readers of KV done
        // Load K tile transposed: KV[d][c]
        {
            int c  = tid & 63;
            int d0 = (tid >> 6) * 16;
            const float* src = K + baseoff + (size_t)(k0 + c) * D_DIM + d0;
#pragma unroll
            for (int i = 0; i < 16; i += 4) {
                float4 v = *(const float4*)(src + i);
                KV[(d0 + i + 0) * PAD + c] = v.x;
                KV[(d0 + i + 1) * PAD + c] = v.y;
                KV[(d0 + i + 2) * PAD + c] = v.z;
                KV[(d0 + i + 3) * PAD + c] = v.w;
            }
        }
        __syncthreads();  // (b) K ready, Q ready

        // S = (Q K^T) * 1/8, causal mask on diagonal tile
        float Sv[4][4];
#pragma unroll
        for (int i = 0; i < 4; i++)
#pragma unroll
            for (int j = 0; j < 4; j++) Sv[i][j] = 0.0f;

#pragma unroll
        for (int d0 = 0; d0 < 64; d0 += 4) {
            float4 q4[4], k4[4];
#pragma unroll
            for (int i = 0; i < 4; i++)
                q4[i] = *(const float4*)&Qs[(ty * 4 + i) * PAD + d0];
#pragma unroll
            for (int dd = 0; dd < 4; dd++)
                k4[dd] = *(const float4*)&KV[(d0 + dd) * PAD + tx * 4];
#pragma unroll
            for (int i = 0; i < 4; i++) {
                const float* qv = (const float*)&q4[i];
#pragma unroll
                for (int dd = 0; dd < 4; dd++) {
                    const float* kv = (const float*)&k4[dd];
#pragma unroll
                    for (int j = 0; j < 4; j++)
                        Sv[i][j] += qv[dd] * kv[j];
                }
            }
        }
        const bool diag = (t == nt - 1);
#pragma unroll
        for (int i = 0; i < 4; i++) {
            int qi = q0 + ty * 4 + i;
#pragma unroll
            for (int j = 0; j < 4; j++) {
                int kj = k0 + tx * 4 + j;
                float s = Sv[i][j] * 0.125f;
                if (diag && kj > qi) s = -1e30f;
                Sv[i][j] = s;
            }
        }

        // row max partials
#pragma unroll
        for (int i = 0; i < 4; i++) {
            float pm = Sv[i][0];
            pm = fmaxf(pm, Sv[i][1]);
            pm = fmaxf(pm, Sv[i][2]);
            pm = fmaxf(pm, Sv[i][3]);
            red[(ty * 4 + i) * 16 + tx] = pm;
        }
        __syncthreads();  // (c)
        if (tid < 64) {
            float tmax = red[tid * 16];
#pragma unroll
            for (int q = 1; q < 16; q++) tmax = fmaxf(tmax, red[tid * 16 + q]);
            float mnew = fmaxf(mrow[tid], tmax);
            crow[tid] = __expf(mrow[tid] - mnew);
            mrow[tid] = mnew;
        }
        __syncthreads();  // (d)

        // P = exp(S - m), write to Ps, accumulate row sums, rescale O
#pragma unroll
        for (int i = 0; i < 4; i++) {
            int r = ty * 4 + i;
            float mn = mrow[r];
            float p0 = __expf(Sv[i][0] - mn);
            float p1 = __expf(Sv[i][1] - mn);
            float p2 = __expf(Sv[i][2] - mn);
            float p3 = __expf(Sv[i][3] - mn);
            *(float4*)&Ps[r * PAD + tx * 4] = make_float4(p0, p1, p2, p3);
            red[r * 16 + tx] = p0 + p1 + p2 + p3;
            float cf = crow[r];
            Oa[i][0] *= cf; Oa[i][1] *= cf; Oa[i][2] *= cf; Oa[i][3] *= cf;
        }
        __syncthreads();  // (e)
        if (tid < 64) {
            float ts = 0.0f;
#pragma unroll
            for (int q = 0; q < 16; q++) ts += red[tid * 16 + q];
            lrow[tid] = lrow[tid] * crow[tid] + ts;
        }
        // Load V tile into KV buffer ([k][d]) — safe: KV no longer read
        {
            int r  = tid >> 2;
            int d0 = (tid & 3) * 16;
            const float* src = V + baseoff + (size_t)(k0 + r) * D_DIM + d0;
#pragma unroll
            for (int i = 0; i < 4; i++)
                *(float4*)&KV[r * PAD + d0 + i * 4] = *(const float4*)(src + i * 4);
        }
        __syncthreads();  // (f) V + l ready

        // O += P @ V
#pragma unroll
        for (int kk = 0; kk < 64; kk += 4) {
            float4 p4[4], v4[4];
#pragma unroll
            for (int i = 0; i < 4; i++)
                p4[i] = *(const float4*)&Ps[(ty * 4 + i) * PAD + kk];
#pragma unroll
            for (int dd = 0; dd < 4; dd++)
                v4[dd] = *(const float4*)&KV[(kk + dd) * PAD + tx * 4];
#pragma unroll
            for (int i = 0; i < 4; i++) {
                const float* pv = (const float*)&p4[i];
#pragma unroll
                for (int dd = 0; dd < 4; dd++) {
                    const float* vv = (const float*)&v4[dd];
#pragma unroll
                    for (int j = 0; j < 4; j++)
                        Oa[i][j] += pv[dd] * vv[j];
                }
            }
        }
    }

    // epilogue: O / l, write to (B,S,D) layout
#pragma unroll
    for (int i = 0; i < 4; i++) {
        int r = ty * 4 + i;
        float inv = 1.0f / lrow[r];
        float4 o = make_float4(Oa[i][0] * inv, Oa[i][1] * inv,
                               Oa[i][2] * inv, Oa[i][3] * inv);
        *(float4*)(Ao + baseoff + (size_t)(q0 + r) * D_DIM + tx * 4) = o;
    }
}

#define FLASH_SMEM ((3 * 64 * PAD + 64 * 16 + 3 * 64) * (int)sizeof(float))

extern "C" void kernel_launch(void* const* d_in, const int* in_sizes, int n_in,
                              void* d_out, int out_size)
{
    (void)in_sizes; (void)n_in; (void)out_size;
    const float* x  = (const float*)d_in[0];
    const float* WQ = (const float*)d_in[1];
    const float* WK = (const float*)d_in[2];
    const float* WV = (const float*)d_in[3];
    const float* WO = (const float*)d_in[4];
    // d_in[5] = mask (causal) — implemented analytically, unused.
    float* out = (float*)d_out;

    float *Qp, *Kp, *Vp, *Ap;
    cudaGetSymbolAddress((void**)&Qp, g_Q);
    cudaGetSymbolAddress((void**)&Kp, g_K);
    cudaGetSymbolAddress((void**)&Vp, g_V);
    cudaGetSymbolAddress((void**)&Ap, g_A);

    dim3 gg(D_DIM / 128, M_TOT / 128);
    sgemm128<<<gg, 256>>>(x, WQ, Qp, M_TOT, D_DIM, D_DIM);
    sgemm128<<<gg, 256>>>(x, WK, Kp, M_TOT, D_DIM, D_DIM);
    sgemm128<<<gg, 256>>>(x, WV, Vp, M_TOT, D_DIM, D_DIM);

    cudaFuncSetAttribute(flash_fp32, cudaFuncAttributeMaxDynamicSharedMemorySize,
                         FLASH_SMEM);
    flash_fp32<<<dim3(S_LEN / 64, H_NUM, B_NUM), 256, FLASH_SMEM>>>(Qp, Kp, Vp, Ap);

    sgemm128<<<gg, 256>>>(Ap, WO, out, M_TOT, D_DIM, D_DIM);
}

// round 8
// speedup vs baseline: 1.4459x; 1.4459x over previous
#include <cuda_runtime.h>
#include <cuda_bf16.h>
#include <cstdint>

#define S_LEN 2048
#define D_DIM 1024
#define H_NUM 16
#define HD    64
#define B_NUM 2
#define M_TOT (B_NUM * S_LEN)   // 4096

// Scratch (static device globals; no runtime allocation)
__device__ float g_Q[(size_t)M_TOT * D_DIM];
__device__ float g_K[(size_t)M_TOT * D_DIM];
__device__ float g_V[(size_t)M_TOT * D_DIM];
__device__ float g_A[(size_t)M_TOT * D_DIM];
// hi/lo bf16 splits of activations
__device__ __nv_bfloat16 g_Xh[(size_t)M_TOT * D_DIM];
__device__ __nv_bfloat16 g_Xl[(size_t)M_TOT * D_DIM];
__device__ __nv_bfloat16 g_AOh[(size_t)M_TOT * D_DIM];
__device__ __nv_bfloat16 g_AOl[(size_t)M_TOT * D_DIM];
// Transposed + hi/lo-split weights (bf16, [N][K])
__device__ __nv_bfloat16 g_WQh[(size_t)D_DIM * D_DIM];
__device__ __nv_bfloat16 g_WQl[(size_t)D_DIM * D_DIM];
__device__ __nv_bfloat16 g_WKh[(size_t)D_DIM * D_DIM];
__device__ __nv_bfloat16 g_WKl[(size_t)D_DIM * D_DIM];
__device__ __nv_bfloat16 g_WVh[(size_t)D_DIM * D_DIM];
__device__ __nv_bfloat16 g_WVl[(size_t)D_DIM * D_DIM];
__device__ __nv_bfloat16 g_WOh[(size_t)D_DIM * D_DIM];
__device__ __nv_bfloat16 g_WOl[(size_t)D_DIM * D_DIM];

// ---------------------------------------------------------------------------
// helpers (base sm_103-safe PTX only: mma.sync / ldmatrix / cp.async)
// ---------------------------------------------------------------------------
__device__ __forceinline__ uint32_t smem_u32(const void* p) {
    uint32_t a;
    asm("{ .reg .u64 t; cvta.to.shared.u64 t, %1; cvt.u32.u64 %0, t; }"
        : "=r"(a) : "l"(p));
    return a;
}
__device__ __forceinline__ void cpa16(uint32_t dst, const void* src) {
    asm volatile("cp.async.cg.shared.global [%0], [%1], 16;"
                 :: "r"(dst), "l"(src) : "memory");
}
__device__ __forceinline__ void cpa_commit() {
    asm volatile("cp.async.commit_group;" ::: "memory");
}
template <int N> __device__ __forceinline__ void cpa_wait() {
    asm volatile("cp.async.wait_group %0;" :: "n"(N) : "memory");
}
__device__ __forceinline__ void ldsm4(uint32_t* r, uint32_t addr) {
    asm volatile("ldmatrix.sync.aligned.m8n8.x4.shared.b16 {%0,%1,%2,%3}, [%4];"
                 : "=r"(r[0]), "=r"(r[1]), "=r"(r[2]), "=r"(r[3]) : "r"(addr));
}
__device__ __forceinline__ void mma16816(float* c, const uint32_t* a,
                                         uint32_t b0, uint32_t b1) {
    asm volatile(
        "mma.sync.aligned.m16n8k16.row.col.f32.bf16.bf16.f32 "
        "{%0,%1,%2,%3}, {%4,%5,%6,%7}, {%8,%9}, {%0,%1,%2,%3};"
        : "+f"(c[0]), "+f"(c[1]), "+f"(c[2]), "+f"(c[3])
        : "r"(a[0]), "r"(a[1]), "r"(a[2]), "r"(a[3]), "r"(b0), "r"(b1));
}

// ---------------------------------------------------------------------------
// split: fp32 -> bf16 hi + bf16 residual
// ---------------------------------------------------------------------------
__global__ __launch_bounds__(256) void split_fp32(
    const float* __restrict__ X,
    __nv_bfloat16* __restrict__ H, __nv_bfloat16* __restrict__ L)
{
    const int i = (blockIdx.x * 256 + threadIdx.x) * 4;
    float4 v = *(const float4*)(X + i);
    float f[4] = {v.x, v.y, v.z, v.w};
    __nv_bfloat16 h[4], l[4];
#pragma unroll
    for (int e = 0; e < 4; e++) {
        h[e] = __float2bfloat16(f[e]);
        l[e] = __float2bfloat16(f[e] - __bfloat162float(h[e]));
    }
    *(uint2*)(H + i) = *(const uint2*)h;
    *(uint2*)(L + i) = *(const uint2*)l;
}

// ---------------------------------------------------------------------------
// Transpose + hi/lo split weights: Th[n][k] = bf16(W[k][n]), Tl = residual.
// ---------------------------------------------------------------------------
__global__ __launch_bounds__(256) void transpose_split(
    const float* __restrict__ W,
    __nv_bfloat16* __restrict__ Th, __nv_bfloat16* __restrict__ Tl)
{
    __shared__ float tile[32][33];
    const int n0 = blockIdx.x * 32, k0 = blockIdx.y * 32;
    const int tx = threadIdx.x, ty = threadIdx.y;   // (32, 8)
#pragma unroll
    for (int i = 0; i < 32; i += 8)
        tile[ty + i][tx] = W[(size_t)(k0 + ty + i) * D_DIM + n0 + tx];
    __syncthreads();
#pragma unroll
    for (int i = 0; i < 32; i += 8) {
        float v = tile[tx][ty + i];
        __nv_bfloat16 h = __float2bfloat16(v);
        __nv_bfloat16 l = __float2bfloat16(v - __bfloat162float(h));
        size_t o = (size_t)(n0 + ty + i) * D_DIM + k0 + tx;
        Th[o] = h;
        Tl[o] = l;
    }
}

// ---------------------------------------------------------------------------
// bf16x3 HMMA GEMM: C[4096,1024] = (Ah+Al)[M][K] @ (Bh+Bl)^T ([N][K] given).
// CTA 128x128, K-chunk 32, 2-stage cp.async pipeline, 8 warps (2x4),
// warp tile 64x32, mma.m16n8k16, products Ah*Bh + Ah*Bl + Al*Bh.
// smem rows padded to 40 halfs (80B) -> conflict-free ldmatrix.
// ---------------------------------------------------------------------------
#define LDH_B 80                 // bytes per smem row
#define ARR_BYTES (128 * LDH_B)  // 10240 per array
#define STG_BYTES (4 * ARR_BYTES)
#define OFF_AH 0
#define OFF_AL ARR_BYTES
#define OFF_BH (2 * ARR_BYTES)
#define OFF_BL (3 * ARR_BYTES)
#define GEMM_SMEM (2 * STG_BYTES)
#define NSTAGE (D_DIM / 32)      // 32

__global__ __launch_bounds__(256) void gemm_mma(
    const __nv_bfloat16* __restrict__ Ah, const __nv_bfloat16* __restrict__ Al,
    const __nv_bfloat16* __restrict__ Bh, const __nv_bfloat16* __restrict__ Bl,
    float* __restrict__ C)
{
    extern __shared__ char smraw[];
    const uint32_t smb = smem_u32(smraw);
    const int tid = threadIdx.x, lane = tid & 31, wid = tid >> 5;
    const int wm = wid >> 2, wn = wid & 3;
    const int bm = blockIdx.y, bn = blockIdx.x;

    float acc[4][4][4];
#pragma unroll
    for (int i = 0; i < 4; i++)
#pragma unroll
        for (int j = 0; j < 4; j++)
#pragma unroll
            for (int e = 0; e < 4; e++) acc[i][j][e] = 0.0f;

#define ISSUE_STAGE(s)                                                        \
    {                                                                         \
        const uint32_t sb_ = smb + ((s) & 1) * STG_BYTES;                     \
        _Pragma("unroll")                                                     \
        for (int q = 0; q < 2; q++) {                                         \
            const int id = tid + q * 256;                                     \
            const int r = id >> 2, c = id & 3;                                \
            const uint32_t off = (uint32_t)(r * LDH_B + c * 16);              \
            const size_t ga = (size_t)(bm * 128 + r) * D_DIM + (s) * 32 + c * 8; \
            const size_t gb = (size_t)(bn * 128 + r) * D_DIM + (s) * 32 + c * 8; \
            cpa16(sb_ + OFF_AH + off, Ah + ga);                               \
            cpa16(sb_ + OFF_AL + off, Al + ga);                               \
            cpa16(sb_ + OFF_BH + off, Bh + gb);                               \
            cpa16(sb_ + OFF_BL + off, Bl + gb);                               \
        }                                                                     \
        cpa_commit();                                                         \
    }

    ISSUE_STAGE(0);

    for (int s = 0; s < NSTAGE; s++) {
        if (s + 1 < NSTAGE) {
            ISSUE_STAGE(s + 1);
            cpa_wait<1>();
        } else {
            cpa_wait<0>();
        }
        __syncthreads();

        const uint32_t sb = smb + (s & 1) * STG_BYTES;
        const uint32_t arow = (uint32_t)((wm * 64 + (lane & 15)) * LDH_B +
                                         (lane >> 4) * 16);
        const uint32_t brow = (uint32_t)((wn * 32 + ((lane >> 4) & 1) * 8 +
                                          (lane & 7)) * LDH_B +
                                         ((lane >> 3) & 1) * 16);
#pragma unroll
        for (int ks = 0; ks < 2; ks++) {
            uint32_t ah[4][4], al[4][4], bh[4][2], bl[4][2];
#pragma unroll
            for (int mt = 0; mt < 4; mt++) {
                const uint32_t ao = arow + (uint32_t)(mt * 16 * LDH_B + ks * 32);
                ldsm4(ah[mt], sb + OFF_AH + ao);
                ldsm4(al[mt], sb + OFF_AL + ao);
            }
#pragma unroll
            for (int t = 0; t < 2; t++) {
                uint32_t r4[4];
                const uint32_t bo = brow + (uint32_t)(t * 16 * LDH_B + ks * 32);
                ldsm4(r4, sb + OFF_BH + bo);
                bh[2 * t][0] = r4[0]; bh[2 * t][1] = r4[1];
                bh[2 * t + 1][0] = r4[2]; bh[2 * t + 1][1] = r4[3];
                ldsm4(r4, sb + OFF_BL + bo);
                bl[2 * t][0] = r4[0]; bl[2 * t][1] = r4[1];
                bl[2 * t + 1][0] = r4[2]; bl[2 * t + 1][1] = r4[3];
            }
#pragma unroll
            for (int mt = 0; mt < 4; mt++)
#pragma unroll
                for (int nt = 0; nt < 4; nt++) {
                    mma16816(acc[mt][nt], ah[mt], bh[nt][0], bh[nt][1]);
                    mma16816(acc[mt][nt], ah[mt], bl[nt][0], bl[nt][1]);
                    mma16816(acc[mt][nt], al[mt], bh[nt][0], bh[nt][1]);
                }
        }
        __syncthreads();
    }

    // epilogue
    const int rg = lane >> 2, cg = (lane & 3) * 2;
#pragma unroll
    for (int mt = 0; mt < 4; mt++) {
        const int row = bm * 128 + wm * 64 + mt * 16 + rg;
#pragma unroll
        for (int nt = 0; nt < 4; nt++) {
            const int col = bn * 128 + wn * 32 + nt * 8 + cg;
            *(float2*)(C + (size_t)row * D_DIM + col) =
                make_float2(acc[mt][nt][0], acc[mt][nt][1]);
            *(float2*)(C + (size_t)(row + 8) * D_DIM + col) =
                make_float2(acc[mt][nt][2], acc[mt][nt][3]);
        }
    }
#undef ISSUE_STAGE
}

// ---------------------------------------------------------------------------
// Flash attention (fp32, causal) — unchanged.
// ---------------------------------------------------------------------------
#define PAD 68

__global__ __launch_bounds__(256) void flash_fp32(const float* __restrict__ Q,
                                                  const float* __restrict__ K,
                                                  const float* __restrict__ V,
                                                  float* __restrict__ Ao)
{
    extern __shared__ __align__(16) float sm[];
    float* Qs   = sm;
    float* KV   = Qs + 64 * PAD;
    float* Ps   = KV + 64 * PAD;
    float* red  = Ps + 64 * PAD;
    float* mrow = red + 64 * 16;
    float* lrow = mrow + 64;
    float* crow = lrow + 64;

    const int tid = threadIdx.x;
    const int ty = tid >> 4;
    const int tx = tid & 15;
    const int q0 = blockIdx.x * 64;
    const int h  = blockIdx.y;
    const int b  = blockIdx.z;
    const size_t baseoff = (size_t)b * S_LEN * D_DIM + (size_t)h * HD;

    {
        int r  = tid >> 2;
        int d0 = (tid & 3) * 16;
        const float* src = Q + baseoff + (size_t)(q0 + r) * D_DIM + d0;
#pragma unroll
        for (int i = 0; i < 4; i++)
            *(float4*)&Qs[r * PAD + d0 + i * 4] = *(const float4*)(src + i * 4);
    }
    if (tid < 64) { mrow[tid] = -1e30f; lrow[tid] = 0.0f; }

    float Oa[4][4];
#pragma unroll
    for (int i = 0; i < 4; i++)
#pragma unroll
        for (int j = 0; j < 4; j++) Oa[i][j] = 0.0f;

    const int nt = q0 / 64 + 1;

    for (int t = 0; t < nt; t++) {
        const int k0 = t * 64;

        __syncthreads();
        {
            int c  = tid & 63;
            int d0 = (tid >> 6) * 16;
            const float* src = K + baseoff + (size_t)(k0 + c) * D_DIM + d0;
#pragma unroll
            for (int i = 0; i < 16; i += 4) {
                float4 v = *(const float4*)(src + i);
                KV[(d0 + i + 0) * PAD + c] = v.x;
                KV[(d0 + i + 1) * PAD + c] = v.y;
                KV[(d0 + i + 2) * PAD + c] = v.z;
                KV[(d0 + i + 3) * PAD + c] = v.w;
            }
        }
        __syncthreads();

        float Sv[4][4];
#pragma unroll
        for (int i = 0; i < 4; i++)
#pragma unroll
            for (int j = 0; j < 4; j++) Sv[i][j] = 0.0f;

#pragma unroll
        for (int d0 = 0; d0 < 64; d0 += 4) {
            float4 q4[4], k4[4];
#pragma unroll
            for (int i = 0; i < 4; i++)
                q4[i] = *(const float4*)&Qs[(ty * 4 + i) * PAD + d0];
#pragma unroll
            for (int dd = 0; dd < 4; dd++)
                k4[dd] = *(const float4*)&KV[(d0 + dd) * PAD + tx * 4];
#pragma unroll
            for (int i = 0; i < 4; i++) {
                const float* qv = (const float*)&q4[i];
#pragma unroll
                for (int dd = 0; dd < 4; dd++) {
                    const float* kv = (const float*)&k4[dd];
#pragma unroll
                    for (int j = 0; j < 4; j++)
                        Sv[i][j] += qv[dd] * kv[j];
                }
            }
        }
        const bool diag = (t == nt - 1);
#pragma unroll
        for (int i = 0; i < 4; i++) {
            int qi = q0 + ty * 4 + i;
#pragma unroll
            for (int j = 0; j < 4; j++) {
                int kj = k0 + tx * 4 + j;
                float s = Sv[i][j] * 0.125f;
                if (diag && kj > qi) s = -1e30f;
                Sv[i][j] = s;
            }
        }

#pragma unroll
        for (int i = 0; i < 4; i++) {
            float pm = Sv[i][0];
            pm = fmaxf(pm, Sv[i][1]);
            pm = fmaxf(pm, Sv[i][2]);
            pm = fmaxf(pm, Sv[i][3]);
            red[(ty * 4 + i) * 16 + tx] = pm;
        }
        __syncthreads();
        if (tid < 64) {
            float tmax = red[tid * 16];
#pragma unroll
            for (int q = 1; q < 16; q++) tmax = fmaxf(tmax, red[tid * 16 + q]);
            float mnew = fmaxf(mrow[tid], tmax);
            crow[tid] = __expf(mrow[tid] - mnew);
            mrow[tid] = mnew;
        }
        __syncthreads();

#pragma unroll
        for (int i = 0; i < 4; i++) {
            int r = ty * 4 + i;
            float mn = mrow[r];
            float p0 = __expf(Sv[i][0] - mn);
            float p1 = __expf(Sv[i][1] - mn);
            float p2 = __expf(Sv[i][2] - mn);
            float p3 = __expf(Sv[i][3] - mn);
            *(float4*)&Ps[r * PAD + tx * 4] = make_float4(p0, p1, p2, p3);
            red[r * 16 + tx] = p0 + p1 + p2 + p3;
            float cf = crow[r];
            Oa[i][0] *= cf; Oa[i][1] *= cf; Oa[i][2] *= cf; Oa[i][3] *= cf;
        }
        __syncthreads();
        if (tid < 64) {
            float ts = 0.0f;
#pragma unroll
            for (int q = 0; q < 16; q++) ts += red[tid * 16 + q];
            lrow[tid] = lrow[tid] * crow[tid] + ts;
        }
        {
            int r  = tid >> 2;
            int d0 = (tid & 3) * 16;
            const float* src = V + baseoff + (size_t)(k0 + r) * D_DIM + d0;
#pragma unroll
            for (int i = 0; i < 4; i++)
                *(float4*)&KV[r * PAD + d0 + i * 4] = *(const float4*)(src + i * 4);
        }
        __syncthreads();

#pragma unroll
        for (int kk = 0; kk < 64; kk += 4) {
            float4 p4[4], v4[4];
#pragma unroll
            for (int i = 0; i < 4; i++)
                p4[i] = *(const float4*)&Ps[(ty * 4 + i) * PAD + kk];
#pragma unroll
            for (int dd = 0; dd < 4; dd++)
                v4[dd] = *(const float4*)&KV[(kk + dd) * PAD + tx * 4];
#pragma unroll
            for (int i = 0; i < 4; i++) {
                const float* pv = (const float*)&p4[i];
#pragma unroll
                for (int dd = 0; dd < 4; dd++) {
                    const float* vv = (const float*)&v4[dd];
#pragma unroll
                    for (int j = 0; j < 4; j++)
                        Oa[i][j] += pv[dd] * vv[j];
                }
            }
        }
    }

#pragma unroll
    for (int i = 0; i < 4; i++) {
        int r = ty * 4 + i;
        float inv = 1.0f / lrow[r];
        float4 o = make_float4(Oa[i][0] * inv, Oa[i][1] * inv,
                               Oa[i][2] * inv, Oa[i][3] * inv);
        *(float4*)(Ao + baseoff + (size_t)(q0 + r) * D_DIM + tx * 4) = o;
    }
}

#define FLASH_SMEM ((3 * 64 * PAD + 64 * 16 + 3 * 64) * (int)sizeof(float))

extern "C" void kernel_launch(void* const* d_in, const int* in_sizes, int n_in,
                              void* d_out, int out_size)
{
    (void)in_sizes; (void)n_in; (void)out_size;
    const float* x  = (const float*)d_in[0];
    const float* WQ = (const float*)d_in[1];
    const float* WK = (const float*)d_in[2];
    const float* WV = (const float*)d_in[3];
    const float* WO = (const float*)d_in[4];
    float* out = (float*)d_out;

    float *Qp, *Kp, *Vp, *Ap;
    cudaGetSymbolAddress((void**)&Qp, g_Q);
    cudaGetSymbolAddress((void**)&Kp, g_K);
    cudaGetSymbolAddress((void**)&Vp, g_V);
    cudaGetSymbolAddress((void**)&Ap, g_A);
    __nv_bfloat16 *Xh, *Xl, *AOh, *AOl;
    cudaGetSymbolAddress((void**)&Xh, g_Xh);
    cudaGetSymbolAddress((void**)&Xl, g_Xl);
    cudaGetSymbolAddress((void**)&AOh, g_AOh);
    cudaGetSymbolAddress((void**)&AOl, g_AOl);
    __nv_bfloat16 *WQh, *WQl, *WKh, *WKl, *WVh, *WVl, *WOh, *WOl;
    cudaGetSymbolAddress((void**)&WQh, g_WQh);
    cudaGetSymbolAddress((void**)&WQl, g_WQl);
    cudaGetSymbolAddress((void**)&WKh, g_WKh);
    cudaGetSymbolAddress((void**)&WKl, g_WKl);
    cudaGetSymbolAddress((void**)&WVh, g_WVh);
    cudaGetSymbolAddress((void**)&WVl, g_WVl);
    cudaGetSymbolAddress((void**)&WOh, g_WOh);
    cudaGetSymbolAddress((void**)&WOl, g_WOl);

    // weight transpose+split and activation split
    dim3 tg(D_DIM / 32, D_DIM / 32);
    dim3 tb(32, 8);
    transpose_split<<<tg, tb>>>(WQ, WQh, WQl);
    transpose_split<<<tg, tb>>>(WK, WKh, WKl);
    transpose_split<<<tg, tb>>>(WV, WVh, WVl);
    transpose_split<<<tg, tb>>>(WO, WOh, WOl);
    split_fp32<<<(M_TOT * D_DIM) / (256 * 4), 256>>>(x, Xh, Xl);

    cudaFuncSetAttribute(gemm_mma, cudaFuncAttributeMaxDynamicSharedMemorySize,
                         GEMM_SMEM);
    dim3 gg(D_DIM / 128, M_TOT / 128);
    gemm_mma<<<gg, 256, GEMM_SMEM>>>(Xh, Xl, WQh, WQl, Qp);
    gemm_mma<<<gg, 256, GEMM_SMEM>>>(Xh, Xl, WKh, WKl, Kp);
    gemm_mma<<<gg, 256, GEMM_SMEM>>>(Xh, Xl, WVh, WVl, Vp);

    cudaFuncSetAttribute(flash_fp32, cudaFuncAttributeMaxDynamicSharedMemorySize,
                         FLASH_SMEM);
    flash_fp32<<<dim3(S_LEN / 64, H_NUM, B_NUM), 256, FLASH_SMEM>>>(Qp, Kp, Vp, Ap);

    split_fp32<<<(M_TOT * D_DIM) / (256 * 4), 256>>>(Ap, AOh, AOl);
    gemm_mma<<<gg, 256, GEMM_SMEM>>>(AOh, AOl, WOh, WOl, out);
}

// round 9
// speedup vs baseline: 2.6477x; 1.8312x over previous
#include <cuda_runtime.h>
#include <cuda_bf16.h>
#include <cstdint>

#define S_LEN 2048
#define D_DIM 1024
#define H_NUM 16
#define HD    64
#define B_NUM 2
#define M_TOT (B_NUM * S_LEN)   // 4096

// log2(e)/8 folded into Q projection
#define QSCALE 0.18033688011112042f

// Scratch (static device globals; no runtime allocation)
__device__ __nv_bfloat16 g_Xh[(size_t)M_TOT * D_DIM];
__device__ __nv_bfloat16 g_Xl[(size_t)M_TOT * D_DIM];
__device__ __nv_bfloat16 g_Qh[(size_t)M_TOT * D_DIM];
__device__ __nv_bfloat16 g_Ql[(size_t)M_TOT * D_DIM];
__device__ __nv_bfloat16 g_Kh[(size_t)M_TOT * D_DIM];
__device__ __nv_bfloat16 g_Kl[(size_t)M_TOT * D_DIM];
__device__ __nv_bfloat16 g_Vh[(size_t)M_TOT * D_DIM];
__device__ __nv_bfloat16 g_Vl[(size_t)M_TOT * D_DIM];
__device__ __nv_bfloat16 g_AOh[(size_t)M_TOT * D_DIM];
__device__ __nv_bfloat16 g_AOl[(size_t)M_TOT * D_DIM];
// Transposed + hi/lo-split weights (bf16, [N][K])
__device__ __nv_bfloat16 g_WQh[(size_t)D_DIM * D_DIM];
__device__ __nv_bfloat16 g_WQl[(size_t)D_DIM * D_DIM];
__device__ __nv_bfloat16 g_WKh[(size_t)D_DIM * D_DIM];
__device__ __nv_bfloat16 g_WKl[(size_t)D_DIM * D_DIM];
__device__ __nv_bfloat16 g_WVh[(size_t)D_DIM * D_DIM];
__device__ __nv_bfloat16 g_WVl[(size_t)D_DIM * D_DIM];
__device__ __nv_bfloat16 g_WOh[(size_t)D_DIM * D_DIM];
__device__ __nv_bfloat16 g_WOl[(size_t)D_DIM * D_DIM];

// ---------------------------------------------------------------------------
// helpers (base sm_103-safe PTX only: mma.sync / ldmatrix / cp.async)
// ---------------------------------------------------------------------------
__device__ __forceinline__ uint32_t smem_u32(const void* p) {
    uint32_t a;
    asm("{ .reg .u64 t; cvta.to.shared.u64 t, %1; cvt.u32.u64 %0, t; }"
        : "=r"(a) : "l"(p));
    return a;
}
__device__ __forceinline__ void cpa16(uint32_t dst, const void* src) {
    asm volatile("cp.async.cg.shared.global [%0], [%1], 16;"
                 :: "r"(dst), "l"(src) : "memory");
}
__device__ __forceinline__ void cpa_commit() {
    asm volatile("cp.async.commit_group;" ::: "memory");
}
template <int N> __device__ __forceinline__ void cpa_wait() {
    asm volatile("cp.async.wait_group %0;" :: "n"(N) : "memory");
}
__device__ __forceinline__ void ldsm4(uint32_t* r, uint32_t addr) {
    asm volatile("ldmatrix.sync.aligned.m8n8.x4.shared.b16 {%0,%1,%2,%3}, [%4];"
                 : "=r"(r[0]), "=r"(r[1]), "=r"(r[2]), "=r"(r[3]) : "r"(addr));
}
__device__ __forceinline__ void ldsm4t(uint32_t* r, uint32_t addr) {
    asm volatile("ldmatrix.sync.aligned.m8n8.x4.trans.shared.b16 {%0,%1,%2,%3}, [%4];"
                 : "=r"(r[0]), "=r"(r[1]), "=r"(r[2]), "=r"(r[3]) : "r"(addr));
}
__device__ __forceinline__ void mma16816(float* c, const uint32_t* a,
                                         uint32_t b0, uint32_t b1) {
    asm volatile(
        "mma.sync.aligned.m16n8k16.row.col.f32.bf16.bf16.f32 "
        "{%0,%1,%2,%3}, {%4,%5,%6,%7}, {%8,%9}, {%0,%1,%2,%3};"
        : "+f"(c[0]), "+f"(c[1]), "+f"(c[2]), "+f"(c[3])
        : "r"(a[0]), "r"(a[1]), "r"(a[2]), "r"(a[3]), "r"(b0), "r"(b1));
}
__device__ __forceinline__ float ex2f(float x) {
    float y;
    asm("ex2.approx.ftz.f32 %0, %1;" : "=f"(y) : "f"(x));
    return y;
}
__device__ __forceinline__ uint32_t packbf(float a, float b) {
    __nv_bfloat162 t = __floats2bfloat162_rn(a, b);
    return *(uint32_t*)&t;
}

// ---------------------------------------------------------------------------
// split: fp32 -> bf16 hi + bf16 residual (activations x)
// ---------------------------------------------------------------------------
__global__ __launch_bounds__(256) void split_fp32(
    const float* __restrict__ X,
    __nv_bfloat16* __restrict__ H, __nv_bfloat16* __restrict__ L)
{
    const int i = (blockIdx.x * 256 + threadIdx.x) * 4;
    float4 v = *(const float4*)(X + i);
    float f[4] = {v.x, v.y, v.z, v.w};
    __nv_bfloat16 h[4], l[4];
#pragma unroll
    for (int e = 0; e < 4; e++) {
        h[e] = __float2bfloat16(f[e]);
        l[e] = __float2bfloat16(f[e] - __bfloat162float(h[e]));
    }
    *(uint2*)(H + i) = *(const uint2*)h;
    *(uint2*)(L + i) = *(const uint2*)l;
}

// ---------------------------------------------------------------------------
// Transpose + hi/lo split weights: Th[n][k] = bf16(W[k][n]), Tl = residual.
// ---------------------------------------------------------------------------
__global__ __launch_bounds__(256) void transpose_split(
    const float* __restrict__ W,
    __nv_bfloat16* __restrict__ Th, __nv_bfloat16* __restrict__ Tl)
{
    __shared__ float tile[32][33];
    const int n0 = blockIdx.x * 32, k0 = blockIdx.y * 32;
    const int tx = threadIdx.x, ty = threadIdx.y;   // (32, 8)
#pragma unroll
    for (int i = 0; i < 32; i += 8)
        tile[ty + i][tx] = W[(size_t)(k0 + ty + i) * D_DIM + n0 + tx];
    __syncthreads();
#pragma unroll
    for (int i = 0; i < 32; i += 8) {
        float v = tile[tx][ty + i];
        __nv_bfloat16 h = __float2bfloat16(v);
        __nv_bfloat16 l = __float2bfloat16(v - __bfloat162float(h));
        size_t o = (size_t)(n0 + ty + i) * D_DIM + k0 + tx;
        Th[o] = h;
        Tl[o] = l;
    }
}

// ---------------------------------------------------------------------------
// bf16x3 HMMA GEMM. OUTM=0: fp32 C out. OUTM=1: bf16 hi/lo out, scaled.
// CTA 128x128, K-chunk 32, 2-stage cp.async pipeline, 8 warps (2x4),
// warp tile 64x32, mma.m16n8k16, products Ah*Bh + Ah*Bl + Al*Bh.
// ---------------------------------------------------------------------------
#define LDH_B 80                 // bytes per smem row
#define ARR_BYTES (128 * LDH_B)
#define STG_BYTES (4 * ARR_BYTES)
#define OFF_AH 0
#define OFF_AL ARR_BYTES
#define OFF_BH (2 * ARR_BYTES)
#define OFF_BL (3 * ARR_BYTES)
#define GEMM_SMEM (2 * STG_BYTES)
#define NSTAGE (D_DIM / 32)      // 32

template <int OUTM>
__global__ __launch_bounds__(256) void gemm_mma(
    const __nv_bfloat16* __restrict__ Ah, const __nv_bfloat16* __restrict__ Al,
    const __nv_bfloat16* __restrict__ Bh, const __nv_bfloat16* __restrict__ Bl,
    float* __restrict__ C,
    __nv_bfloat16* __restrict__ Ch, __nv_bfloat16* __restrict__ Cl,
    float scale)
{
    extern __shared__ char smraw[];
    const uint32_t smb = smem_u32(smraw);
    const int tid = threadIdx.x, lane = tid & 31, wid = tid >> 5;
    const int wm = wid >> 2, wn = wid & 3;
    const int bm = blockIdx.y, bn = blockIdx.x;

    float acc[4][4][4];
#pragma unroll
    for (int i = 0; i < 4; i++)
#pragma unroll
        for (int j = 0; j < 4; j++)
#pragma unroll
            for (int e = 0; e < 4; e++) acc[i][j][e] = 0.0f;

#define ISSUE_STAGE(s)                                                        \
    {                                                                         \
        const uint32_t sb_ = smb + ((s) & 1) * STG_BYTES;                     \
        _Pragma("unroll")                                                     \
        for (int q = 0; q < 2; q++) {                                         \
            const int id = tid + q * 256;                                     \
            const int r = id >> 2, c = id & 3;                                \
            const uint32_t off = (uint32_t)(r * LDH_B + c * 16);              \
            const size_t ga = (size_t)(bm * 128 + r) * D_DIM + (s) * 32 + c * 8; \
            const size_t gb = (size_t)(bn * 128 + r) * D_DIM + (s) * 32 + c * 8; \
            cpa16(sb_ + OFF_AH + off, Ah + ga);                               \
            cpa16(sb_ + OFF_AL + off, Al + ga);                               \
            cpa16(sb_ + OFF_BH + off, Bh + gb);                               \
            cpa16(sb_ + OFF_BL + off, Bl + gb);                               \
        }                                                                     \
        cpa_commit();                                                         \
    }

    ISSUE_STAGE(0);

    for (int s = 0; s < NSTAGE; s++) {
        if (s + 1 < NSTAGE) {
            ISSUE_STAGE(s + 1);
            cpa_wait<1>();
        } else {
            cpa_wait<0>();
        }
        __syncthreads();

        const uint32_t sb = smb + (s & 1) * STG_BYTES;
        const uint32_t arow = (uint32_t)((wm * 64 + (lane & 15)) * LDH_B +
                                         (lane >> 4) * 16);
        const uint32_t brow = (uint32_t)((wn * 32 + ((lane >> 4) & 1) * 8 +
                                          (lane & 7)) * LDH_B +
                                         ((lane >> 3) & 1) * 16);
#pragma unroll
        for (int ks = 0; ks < 2; ks++) {
            uint32_t ah[4][4], al[4][4], bh[4][2], bl[4][2];
#pragma unroll
            for (int mt = 0; mt < 4; mt++) {
                const uint32_t ao = arow + (uint32_t)(mt * 16 * LDH_B + ks * 32);
                ldsm4(ah[mt], sb + OFF_AH + ao);
                ldsm4(al[mt], sb + OFF_AL + ao);
            }
#pragma unroll
            for (int t = 0; t < 2; t++) {
                uint32_t r4[4];
                const uint32_t bo = brow + (uint32_t)(t * 16 * LDH_B + ks * 32);
                ldsm4(r4, sb + OFF_BH + bo);
                bh[2 * t][0] = r4[0]; bh[2 * t][1] = r4[1];
                bh[2 * t + 1][0] = r4[2]; bh[2 * t + 1][1] = r4[3];
                ldsm4(r4, sb + OFF_BL + bo);
                bl[2 * t][0] = r4[0]; bl[2 * t][1] = r4[1];
                bl[2 * t + 1][0] = r4[2]; bl[2 * t + 1][1] = r4[3];
            }
#pragma unroll
            for (int mt = 0; mt < 4; mt++)
#pragma unroll
                for (int nt = 0; nt < 4; nt++) {
                    mma16816(acc[mt][nt], ah[mt], bh[nt][0], bh[nt][1]);
                    mma16816(acc[mt][nt], ah[mt], bl[nt][0], bl[nt][1]);
                    mma16816(acc[mt][nt], al[mt], bh[nt][0], bh[nt][1]);
                }
        }
        __syncthreads();
    }

    // epilogue
    const int rg = lane >> 2, cg = (lane & 3) * 2;
#pragma unroll
    for (int mt = 0; mt < 4; mt++) {
        const int row = bm * 128 + wm * 64 + mt * 16 + rg;
#pragma unroll
        for (int nt = 0; nt < 4; nt++) {
            const int col = bn * 128 + wn * 32 + nt * 8 + cg;
            if (OUTM == 0) {
                *(float2*)(C + (size_t)row * D_DIM + col) =
                    make_float2(acc[mt][nt][0], acc[mt][nt][1]);
                *(float2*)(C + (size_t)(row + 8) * D_DIM + col) =
                    make_float2(acc[mt][nt][2], acc[mt][nt][3]);
            } else {
#pragma unroll
                for (int rh = 0; rh < 2; rh++) {
                    float v0 = acc[mt][nt][2 * rh] * scale;
                    float v1 = acc[mt][nt][2 * rh + 1] * scale;
                    __nv_bfloat16 h0 = __float2bfloat16(v0);
                    __nv_bfloat16 h1 = __float2bfloat16(v1);
                    float l0 = v0 - __bfloat162float(h0);
                    float l1 = v1 - __bfloat162float(h1);
                    const size_t o = (size_t)(row + rh * 8) * D_DIM + col;
                    __nv_bfloat162 hp; hp.x = h0; hp.y = h1;
                    *(uint32_t*)(Ch + o) = *(uint32_t*)&hp;
                    *(uint32_t*)(Cl + o) = packbf(l0, l1);
                }
            }
        }
    }
#undef ISSUE_STAGE
}

// ---------------------------------------------------------------------------
// HMMA flash attention (causal). CTA: 128 q-rows x 1 head. 8 warps x 16 rows.
// Bk=64, K/V double-buffered cp.async. bf16x3 for QK and PV. exp2-domain
// softmax (log2e/8 pre-folded into Q). Writes bf16 hi/lo output.
// smem rows: 64 halfs padded to 144B (conflict-free ldmatrix).
// ---------------------------------------------------------------------------
#define FQ_BYTES (128 * 144)            // 18432 per Q array
#define FKV_ARR  (64 * 144)             // 9216 per K/V array
#define FKV_STG  (4 * FKV_ARR)          // 36864 per stage
#define FLASH_SMEM (2 * FQ_BYTES + 2 * FKV_STG)   // 110592

__global__ __launch_bounds__(256) void flash_mma(
    const __nv_bfloat16* __restrict__ Qh, const __nv_bfloat16* __restrict__ Ql,
    const __nv_bfloat16* __restrict__ Kh, const __nv_bfloat16* __restrict__ Kl,
    const __nv_bfloat16* __restrict__ Vh, const __nv_bfloat16* __restrict__ Vl,
    __nv_bfloat16* __restrict__ Oh, __nv_bfloat16* __restrict__ Ol)
{
    extern __shared__ char fsm[];
    const uint32_t smb = smem_u32(fsm);
    const int tid = threadIdx.x, lane = tid & 31, wm = tid >> 5;
    const int bq = (int)gridDim.x - 1 - (int)blockIdx.x;   // heavy blocks first
    const int hh = blockIdx.y, bb = blockIdx.z;
    const int q0 = bq * 128;
    const int nt = 2 * bq + 2;
    const size_t rowbase = (size_t)bb * S_LEN;
    const int coff = hh * HD;

    const uint32_t QHs = smb, QLs = smb + FQ_BYTES, KVs = smb + 2 * FQ_BYTES;

    // issue Q tile (both arrays)
#pragma unroll
    for (int i = 0; i < 4; i++) {
        int id = tid + i * 256;
        int r = id >> 3, c = id & 7;
        size_t g = (rowbase + q0 + r) * D_DIM + coff + c * 8;
        uint32_t d = (uint32_t)(r * 144 + c * 16);
        cpa16(QHs + d, Qh + g);
        cpa16(QLs + d, Ql + g);
    }

#define ISSUE_KV(t_, st_)                                                    \
    {                                                                        \
        const uint32_t base_ = KVs + (st_) * FKV_STG;                        \
        const int k0_ = (t_) * 64;                                           \
        _Pragma("unroll")                                                    \
        for (int i = 0; i < 2; i++) {                                        \
            int id = tid + i * 256;                                          \
            int r = id >> 3, c = id & 7;                                     \
            size_t g = (rowbase + k0_ + r) * D_DIM + coff + c * 8;           \
            uint32_t d = (uint32_t)(r * 144 + c * 16);                       \
            cpa16(base_ + d, Kh + g);                                        \
            cpa16(base_ + FKV_ARR + d, Kl + g);                              \
            cpa16(base_ + 2 * FKV_ARR + d, Vh + g);                          \
            cpa16(base_ + 3 * FKV_ARR + d, Vl + g);                          \
        }                                                                    \
    }

    ISSUE_KV(0, 0); cpa_commit();
    ISSUE_KV(1, 1); cpa_commit();
    cpa_wait<1>();
    __syncthreads();

    // Q fragments -> registers (stay for whole CTA)
    uint32_t qfh[4][4], qfl[4][4];
    {
        const uint32_t qoff = (uint32_t)((wm * 16 + (lane & 15)) * 144 +
                                         ((lane >> 4) & 1) * 16);
#pragma unroll
        for (int k = 0; k < 4; k++) {
            ldsm4(qfh[k], QHs + qoff + k * 32);
            ldsm4(qfl[k], QLs + qoff + k * 32);
        }
    }

    float O[8][4];
#pragma unroll
    for (int j = 0; j < 8; j++)
#pragma unroll
        for (int e = 0; e < 4; e++) O[j][e] = 0.0f;
    float mo[2] = {-1e30f, -1e30f}, ls[2] = {0.0f, 0.0f};

    const int qb = q0 + wm * 16;

    for (int t = 0; t < nt; t++) {
        const uint32_t sb = KVs + (t & 1) * FKV_STG;
        const int k0 = t * 64;

        // ---- S = Qs K^T (exp2 domain; scale folded into Q) ----
        float S[8][4];
#pragma unroll
        for (int j = 0; j < 8; j++)
#pragma unroll
            for (int e = 0; e < 4; e++) S[j][e] = 0.0f;

        const uint32_t krow = (uint32_t)(((lane & 7) + ((lane >> 4) & 1) * 8) * 144 +
                                         ((lane >> 3) & 1) * 16);
#pragma unroll
        for (int j2 = 0; j2 < 4; j2++) {
#pragma unroll
            for (int k = 0; k < 4; k++) {
                uint32_t bh[4], bl[4];
                const uint32_t ka = sb + krow + (uint32_t)(j2 * 16 * 144 + k * 32);
                ldsm4(bh, ka);
                ldsm4(bl, ka + FKV_ARR);
                mma16816(S[2 * j2], qfh[k], bh[0], bh[1]);
                mma16816(S[2 * j2], qfh[k], bl[0], bl[1]);
                mma16816(S[2 * j2], qfl[k], bh[0], bh[1]);
                mma16816(S[2 * j2 + 1], qfh[k], bh[2], bh[3]);
                mma16816(S[2 * j2 + 1], qfh[k], bl[2], bl[3]);
                mma16816(S[2 * j2 + 1], qfl[k], bh[2], bh[3]);
            }
        }

        // ---- causal mask (only tiles crossing this warp's diagonal) ----
        if (k0 + 63 > qb) {
#pragma unroll
            for (int j = 0; j < 8; j++)
#pragma unroll
                for (int e = 0; e < 4; e++) {
                    int kj = k0 + j * 8 + (lane & 3) * 2 + (e & 1);
                    int qi = qb + (lane >> 2) + (e >> 1) * 8;
                    if (kj > qi) S[j][e] = -1e30f;
                }
        }

        // ---- online softmax (exp2 domain), per row-half ----
#pragma unroll
        for (int rh = 0; rh < 2; rh++) {
            float mx = -1e30f;
#pragma unroll
            for (int j = 0; j < 8; j++) {
                mx = fmaxf(mx, S[j][2 * rh]);
                mx = fmaxf(mx, S[j][2 * rh + 1]);
            }
            mx = fmaxf(mx, __shfl_xor_sync(0xffffffffu, mx, 1));
            mx = fmaxf(mx, __shfl_xor_sync(0xffffffffu, mx, 2));
            const float mn = fmaxf(mo[rh], mx);
            const float cc = ex2f(mo[rh] - mn);
            mo[rh] = mn;
            float ps = 0.0f;
#pragma unroll
            for (int j = 0; j < 8; j++) {
                float p0 = ex2f(S[j][2 * rh] - mn);
                float p1 = ex2f(S[j][2 * rh + 1] - mn);
                S[j][2 * rh] = p0;
                S[j][2 * rh + 1] = p1;
                ps += p0 + p1;
            }
            ps += __shfl_xor_sync(0xffffffffu, ps, 1);
            ps += __shfl_xor_sync(0xffffffffu, ps, 2);
            ls[rh] = ls[rh] * cc + ps;
#pragma unroll
            for (int j = 0; j < 8; j++) {
                O[j][2 * rh] *= cc;
                O[j][2 * rh + 1] *= cc;
            }
        }

        // ---- pack P -> A fragments (hi/lo) ----
        uint32_t aph[4][4], apl[4][4];
#pragma unroll
        for (int k = 0; k < 4; k++)
#pragma unroll
            for (int r = 0; r < 4; r++) {
                const int tl = 2 * k + (r >> 1);
                const int pr = (r & 1) * 2;
                float x0 = S[tl][pr], x1 = S[tl][pr + 1];
                __nv_bfloat16 h0 = __float2bfloat16(x0);
                __nv_bfloat16 h1 = __float2bfloat16(x1);
                __nv_bfloat162 hp; hp.x = h0; hp.y = h1;
                aph[k][r] = *(uint32_t*)&hp;
                apl[k][r] = packbf(x0 - __bfloat162float(h0),
                                   x1 - __bfloat162float(h1));
            }

        // ---- O += P V  (V via ldmatrix.trans) ----
        const uint32_t vrow = (uint32_t)(((lane & 7) + ((lane >> 3) & 1) * 8) * 144 +
                                         ((lane >> 4) & 1) * 16);
#pragma unroll
        for (int dj = 0; dj < 4; dj++) {
#pragma unroll
            for (int k = 0; k < 4; k++) {
                uint32_t bh[4], bl[4];
                const uint32_t va = sb + 2 * FKV_ARR + vrow +
                                    (uint32_t)(k * 16 * 144 + dj * 32);
                ldsm4t(bh, va);
                ldsm4t(bl, va + FKV_ARR);
                mma16816(O[2 * dj], aph[k], bh[0], bh[1]);
                mma16816(O[2 * dj], aph[k], bl[0], bl[1]);
                mma16816(O[2 * dj], apl[k], bh[0], bh[1]);
                mma16816(O[2 * dj + 1], aph[k], bh[2], bh[3]);
                mma16816(O[2 * dj + 1], aph[k], bl[2], bl[3]);
                mma16816(O[2 * dj + 1], apl[k], bh[2], bh[3]);
            }
        }

        __syncthreads();
        if (t + 2 < nt) {
            ISSUE_KV(t + 2, (t & 1));
            cpa_commit();
            cpa_wait<1>();
        } else {
            cpa_wait<0>();
        }
        __syncthreads();
    }

    // ---- epilogue: normalize, split, store bf16 hi/lo ----
    const float inv[2] = {1.0f / ls[0], 1.0f / ls[1]};
#pragma unroll
    for (int j = 0; j < 8; j++)
#pragma unroll
        for (int rh = 0; rh < 2; rh++) {
            float o0 = O[j][2 * rh] * inv[rh];
            float o1 = O[j][2 * rh + 1] * inv[rh];
            __nv_bfloat16 h0 = __float2bfloat16(o0);
            __nv_bfloat16 h1 = __float2bfloat16(o1);
            const size_t row = rowbase + q0 + wm * 16 + (lane >> 2) + rh * 8;
            const int col = coff + j * 8 + (lane & 3) * 2;
            __nv_bfloat162 hp; hp.x = h0; hp.y = h1;
            *(uint32_t*)(Oh + row * D_DIM + col) = *(uint32_t*)&hp;
            *(uint32_t*)(Ol + row * D_DIM + col) =
                packbf(o0 - __bfloat162float(h0), o1 - __bfloat162float(h1));
        }
#undef ISSUE_KV
}

extern "C" void kernel_launch(void* const* d_in, const int* in_sizes, int n_in,
                              void* d_out, int out_size)
{
    (void)in_sizes; (void)n_in; (void)out_size;
    const float* x  = (const float*)d_in[0];
    const float* WQ = (const float*)d_in[1];
    const float* WK = (const float*)d_in[2];
    const float* WV = (const float*)d_in[3];
    const float* WO = (const float*)d_in[4];
    float* out = (float*)d_out;

    __nv_bfloat16 *Xh, *Xl, *Qh, *Ql, *Kh, *Kl, *Vh, *Vl, *AOh, *AOl;
    cudaGetSymbolAddress((void**)&Xh, g_Xh);
    cudaGetSymbolAddress((void**)&Xl, g_Xl);
    cudaGetSymbolAddress((void**)&Qh, g_Qh);
    cudaGetSymbolAddress((void**)&Ql, g_Ql);
    cudaGetSymbolAddress((void**)&Kh, g_Kh);
    cudaGetSymbolAddress((void**)&Kl, g_Kl);
    cudaGetSymbolAddress((void**)&Vh, g_Vh);
    cudaGetSymbolAddress((void**)&Vl, g_Vl);
    cudaGetSymbolAddress((void**)&AOh, g_AOh);
    cudaGetSymbolAddress((void**)&AOl, g_AOl);
    __nv_bfloat16 *WQh, *WQl, *WKh, *WKl, *WVh, *WVl, *WOh, *WOl;
    cudaGetSymbolAddress((void**)&WQh, g_WQh);
    cudaGetSymbolAddress((void**)&WQl, g_WQl);
    cudaGetSymbolAddress((void**)&WKh, g_WKh);
    cudaGetSymbolAddress((void**)&WKl, g_WKl);
    cudaGetSymbolAddress((void**)&WVh, g_WVh);
    cudaGetSymbolAddress((void**)&WVl, g_WVl);
    cudaGetSymbolAddress((void**)&WOh, g_WOh);
    cudaGetSymbolAddress((void**)&WOl, g_WOl);

    // weight transpose+split and activation split
    dim3 tg(D_DIM / 32, D_DIM / 32);
    dim3 tb(32, 8);
    transpose_split<<<tg, tb>>>(WQ, WQh, WQl);
    transpose_split<<<tg, tb>>>(WK, WKh, WKl);
    transpose_split<<<tg, tb>>>(WV, WVh, WVl);
    transpose_split<<<tg, tb>>>(WO, WOh, WOl);
    split_fp32<<<(M_TOT * D_DIM) / (256 * 4), 256>>>(x, Xh, Xl);

    cudaFuncSetAttribute(gemm_mma<0>, cudaFuncAttributeMaxDynamicSharedMemorySize,
                         GEMM_SMEM);
    cudaFuncSetAttribute(gemm_mma<1>, cudaFuncAttributeMaxDynamicSharedMemorySize,
                         GEMM_SMEM);
    dim3 gg(D_DIM / 128, M_TOT / 128);
    // projections emit bf16 hi/lo directly; Q carries log2e/8
    gemm_mma<1><<<gg, 256, GEMM_SMEM>>>(Xh, Xl, WQh, WQl, nullptr, Qh, Ql, QSCALE);
    gemm_mma<1><<<gg, 256, GEMM_SMEM>>>(Xh, Xl, WKh, WKl, nullptr, Kh, Kl, 1.0f);
    gemm_mma<1><<<gg, 256, GEMM_SMEM>>>(Xh, Xl, WVh, WVl, nullptr, Vh, Vl, 1.0f);

    cudaFuncSetAttribute(flash_mma, cudaFuncAttributeMaxDynamicSharedMemorySize,
                         FLASH_SMEM);
    flash_mma<<<dim3(S_LEN / 128, H_NUM, B_NUM), 256, FLASH_SMEM>>>(
        Qh, Ql, Kh, Kl, Vh, Vl, AOh, AOl);

    gemm_mma<0><<<gg, 256, GEMM_SMEM>>>(AOh, AOl, WOh, WOl, out, nullptr, nullptr,
                                        1.0f);
}